// round 8
// baseline (speedup 1.0000x reference)
#include <cuda_runtime.h>
#include <cuda_fp16.h>
#include <math.h>
#include <stdint.h>

// ---------------- sizes (fixed) ----------------
#define ROWS   8192
#define DMODEL 512
#define HDH    4096
#define SEQ    1024
#define NHB    64

// ---------------- scratch ----------------------
static __device__ __half g_q16[4194304];    // [8192, 512]
static __device__ __half g_k16[4194304];
static __device__ __half g_v16[4194304];
static __device__ __half g_wqt16[2097152];  // [4096, 512]  W^T
static __device__ __half g_wkt16[2097152];
static __device__ __half g_wvt16[2097152];
static __device__ __half g_wot16[2097152];  // [512, 4096]
static __device__ __half g_qh16[33554432];  // [8192, 4096]
static __device__ __half g_kh16[33554432];
static __device__ __half g_vh16[33554432];
static __device__ __half g_vht16[33554432]; // [64][512][1024]
static __device__ __half g_sc16[67108864];  // [64, 1024, 1024] scores fp16
static __device__ __half g_pr16[67108864];  // probs fp16
static __device__ __half g_ao16[33554432];  // [8192, 4096]
static __device__ float  g_og[4194304];     // [8192, 512]

// ---------------- helpers ----------------------
__device__ __forceinline__ uint32_t smem_u32(const void* p) {
    uint32_t a;
    asm("{ .reg .u64 t; cvta.to.shared.u64 t, %1; cvt.u32.u64 %0, t; }" : "=r"(a) : "l"(p));
    return a;
}
__device__ __forceinline__ void mma16816(
    float& c0, float& c1, float& c2, float& c3,
    uint32_t a0, uint32_t a1, uint32_t a2, uint32_t a3,
    uint32_t b0, uint32_t b1)
{
    asm volatile(
        "mma.sync.aligned.m16n8k16.row.col.f32.f16.f16.f32 "
        "{%0,%1,%2,%3}, {%4,%5,%6,%7}, {%8,%9}, {%0,%1,%2,%3};"
        : "+f"(c0), "+f"(c1), "+f"(c2), "+f"(c3)
        : "r"(a0), "r"(a1), "r"(a2), "r"(a3), "r"(b0), "r"(b1));
}
#define LDSM4(r, a) \
    asm volatile("ldmatrix.sync.aligned.m8n8.x4.shared.b16 {%0,%1,%2,%3}, [%4];" \
                 : "=r"((r)[0]), "=r"((r)[1]), "=r"((r)[2]), "=r"((r)[3]) : "r"(a))

// ---------------- fp16 tensor-core GEMM ----------------
// C[m,n] = alpha * sum_k A[m,k] * B[n,k]   (both operands K-major fp16)
// CTA 128 x TN, BK=64 halfs (128B rows, XOR-swizzled), 3-stage cp.async,
// THREADS = 2*TN, warps in 2 x (TN/32) grid, warp tile 64x32 (proven config).
// TN=128: 256 thr, 2 CTAs/SM (== round-5 kernel). TN=256: 512 thr, 1 CTA/SM,
// same 16 resident warps, half the per-FLOP B smem traffic.
#define NSTG 3

template <typename CT, int TN>
__global__ __launch_bounds__(2 * TN, (TN == 128) ? 2 : 1)
void k_gemm_h(
    const __half* __restrict__ A, int lda, size_t Az1, size_t Az2,
    const __half* __restrict__ B, int ldb, size_t Bz1, size_t Bz2,
    CT* __restrict__ C, int ldc, size_t Cz1, size_t Cz2,
    int K, float alpha)
{
    extern __shared__ __align__(128) char dyn[];
    constexpr int THREADS = 2 * TN;
    constexpr int ABYTES  = 128 * 128;          // 16 KB
    constexpr int STAGEB  = ABYTES + TN * 128;
    constexpr int WCOLS   = TN / 32;            // warp grid columns
    constexpr int RSTEP   = THREADS / 8;        // rows loaded per pass

    const int z1 = blockIdx.z >> 3, z2 = blockIdx.z & 7;
    A += z1 * Az1 + z2 * Az2 + (size_t)blockIdx.y * 128 * lda;
    B += z1 * Bz1 + z2 * Bz2 + (size_t)blockIdx.x * TN * ldb;
    C += z1 * Cz1 + z2 * Cz2 + (size_t)blockIdx.y * 128 * ldc + (size_t)blockIdx.x * TN;

    const int tid  = threadIdx.x;
    const int warp = tid >> 5;
    const int lane = tid & 31;
    const int g    = lane >> 2;
    const int tg   = lane & 3;
    const int wm   = (warp / WCOLS) * 64;
    const int wn   = (warp % WCOLS) * 32;
    const int lr   = tid >> 3;        // 0..THREADS/8-1 (+RSTEP*i)
    const int c8   = tid & 7;         // 16B chunk index in row

    // ldmatrix lane->row/chunk mapping
    const int la = lane & 15, ha = lane >> 4;                 // A operand
    const int lb = ((lane >> 4) << 3) | (lane & 7);           // B operand row
    const int hb = (lane >> 3) & 1;                           // B chunk bit

    const uint32_t sb = smem_u32(dyn);

    float acc[4][4][4];
#pragma unroll
    for (int mi = 0; mi < 4; mi++)
#pragma unroll
        for (int ni = 0; ni < 4; ni++)
#pragma unroll
            for (int r = 0; r < 4; r++) acc[mi][ni][r] = 0.0f;

    auto issue = [&](int kc, int st) {
        const int k0 = kc << 6;
        const uint32_t sA = sb + st * STAGEB;
        const uint32_t sB = sA + ABYTES;
#pragma unroll
        for (int i = 0; i < 128 / RSTEP; i++) {
            const int r = lr + RSTEP * i;
            const uint32_t d = sA + r * 128 + ((c8 ^ (r & 7)) << 4);
            const void* s = &A[(size_t)r * lda + k0 + c8 * 8];
            asm volatile("cp.async.cg.shared.global [%0], [%1], 16;" :: "r"(d), "l"(s));
        }
#pragma unroll
        for (int i = 0; i < TN / RSTEP; i++) {
            const int r = lr + RSTEP * i;
            const uint32_t d = sB + r * 128 + ((c8 ^ (r & 7)) << 4);
            const void* s = &B[(size_t)r * ldb + k0 + c8 * 8];
            asm volatile("cp.async.cg.shared.global [%0], [%1], 16;" :: "r"(d), "l"(s));
        }
        asm volatile("cp.async.commit_group;" ::: "memory");
    };

    auto compute = [&](int st) {
        const uint32_t sA = sb + st * STAGEB;
        const uint32_t sB = sA + ABYTES;
#pragma unroll
        for (int ks = 0; ks < 4; ks++) {
            uint32_t af[4][4], bf[2][4];
#pragma unroll
            for (int mi = 0; mi < 4; mi++) {
                const int rr = wm + mi * 16 + la;
                const int cc = ks * 2 + ha;
                LDSM4(af[mi], sA + rr * 128 + ((cc ^ (rr & 7)) << 4));
            }
#pragma unroll
            for (int np = 0; np < 2; np++) {
                const int rr = wn + np * 16 + lb;
                const int cc = ks * 2 + hb;
                LDSM4(bf[np], sB + rr * 128 + ((cc ^ (rr & 7)) << 4));
            }
#pragma unroll
            for (int mi = 0; mi < 4; mi++)
#pragma unroll
                for (int ni = 0; ni < 4; ni++) {
                    const int np = ni >> 1, o = (ni & 1) * 2;
                    mma16816(acc[mi][ni][0], acc[mi][ni][1], acc[mi][ni][2], acc[mi][ni][3],
                             af[mi][0], af[mi][1], af[mi][2], af[mi][3],
                             bf[np][o], bf[np][o + 1]);
                }
        }
    };

    const int NK = K >> 6;
    issue(0, 0);
    issue(1, 1);
    for (int kc = 0; kc < NK; kc++) {
        if (kc < NK - 1)
            asm volatile("cp.async.wait_group 1;" ::: "memory");
        else
            asm volatile("cp.async.wait_group 0;" ::: "memory");
        __syncthreads();
        if (kc + 2 < NK) issue(kc + 2, (kc + 2) % NSTG);
        compute(kc % NSTG);
    }

    // epilogue: direct paired stores
#pragma unroll
    for (int mi = 0; mi < 4; mi++) {
        const int r = wm + mi * 16 + g;
#pragma unroll
        for (int ni = 0; ni < 4; ni++) {
            const int c = wn + ni * 8 + tg * 2;
            if constexpr (sizeof(CT) == 2) {
                *(__half2*)&C[(size_t)r * ldc + c] =
                    __floats2half2_rn(alpha * acc[mi][ni][0], alpha * acc[mi][ni][1]);
                *(__half2*)&C[(size_t)(r + 8) * ldc + c] =
                    __floats2half2_rn(alpha * acc[mi][ni][2], alpha * acc[mi][ni][3]);
            } else {
                *(float2*)&C[(size_t)r * ldc + c] =
                    make_float2(alpha * acc[mi][ni][0], alpha * acc[mi][ni][1]);
                *(float2*)&C[(size_t)(r + 8) * ldc + c] =
                    make_float2(alpha * acc[mi][ni][2], alpha * acc[mi][ni][3]);
            }
        }
    }
}

// ---------------- converts / transposes ----------
__global__ __launch_bounds__(256) void k_f2h(
    const float* __restrict__ in, __half* __restrict__ out)
{
    const int i = (blockIdx.x * 256 + threadIdx.x) * 4;
    float4 v = *(const float4*)&in[i];
    ((__half2*)(out + i))[0] = __floats2half2_rn(v.x, v.y);
    ((__half2*)(out + i))[1] = __floats2half2_rn(v.z, v.w);
}

// out[C][R] = in[R][C]^T, fp32 -> fp16.  grid(C/32, R/32), block(32,8)
__global__ void k_wtrans_h(const float* __restrict__ in, __half* __restrict__ out,
                           int R, int C)
{
    __shared__ float t[32][33];
    const int c0 = blockIdx.x * 32, r0 = blockIdx.y * 32;
    const int tx = threadIdx.x, ty = threadIdx.y;
#pragma unroll
    for (int i = 0; i < 32; i += 8)
        t[ty + i][tx] = in[(size_t)(r0 + ty + i) * C + c0 + tx];
    __syncthreads();
#pragma unroll
    for (int i = 0; i < 32; i += 8)
        out[(size_t)(c0 + ty + i) * R + r0 + tx] = __float2half(t[tx][ty + i]);
}

// vht16[h*8+b][d][s] = vh16[b*1024+s][h*512+d]   grid(16, 32, 64), block(32,8)
__global__ void k_vtrans(const __half* __restrict__ vh, __half* __restrict__ vt)
{
    __shared__ __half t[32][33];
    const int z = blockIdx.z, h = z >> 3, b = z & 7;
    const __half* in = vh + (size_t)b * SEQ * HDH + (size_t)h * 512;
    __half* out = vt + (size_t)z * 512 * SEQ;
    const int d0 = blockIdx.x * 32, s0 = blockIdx.y * 32;
    const int tx = threadIdx.x, ty = threadIdx.y;
#pragma unroll
    for (int i = 0; i < 32; i += 8)
        t[ty + i][tx] = in[(size_t)(s0 + ty + i) * HDH + d0 + tx];
    __syncthreads();
#pragma unroll
    for (int i = 0; i < 32; i += 8)
        out[(size_t)(d0 + ty + i) * SEQ + s0 + tx] = t[tx][ty + i];
}

// ---------------- softmax (fp16 in/out, no max pass) -------------
__global__ __launch_bounds__(256) void k_softmax(
    const __half* __restrict__ Sc, const unsigned char* __restrict__ mask,
    __half* __restrict__ Pr)
{
    const int r = blockIdx.x;
    const int q = r & 1023;
    const int b = (r >> 10) & 7;
    const __half* row = Sc + (size_t)r * SEQ;
    __half* prow = Pr + (size_t)r * SEQ;
    const unsigned char* mrow = mask + ((size_t)b * SEQ + q) * SEQ;
    const int tid = threadIdx.x;
    const int c = tid * 4;

    __shared__ float sh2[8];

    const __half2 h01 = ((const __half2*)(row + c))[0];
    const __half2 h23 = ((const __half2*)(row + c))[1];
    const uint32_t m = *(const uint32_t*)&mrow[c];
    float vals[4] = {__low2float(h01), __high2float(h01),
                     __low2float(h23), __high2float(h23)};
    if (m & 0x000000ffu) vals[0] = -1e9f;
    if (m & 0x0000ff00u) vals[1] = -1e9f;
    if (m & 0x00ff0000u) vals[2] = -1e9f;
    if (m & 0xff000000u) vals[3] = -1e9f;

    float sum = 0.0f;
#pragma unroll
    for (int i = 0; i < 4; i++) { vals[i] = expf(vals[i]); sum += vals[i]; }
#pragma unroll
    for (int off = 16; off; off >>= 1) sum += __shfl_xor_sync(0xffffffffu, sum, off);
    if ((tid & 31) == 0) sh2[tid >> 5] = sum;
    __syncthreads();
    sum = 0.0f;
#pragma unroll
    for (int w = 0; w < 8; w++) sum += sh2[w];

    const float inv = 1.0f / sum;
    ((__half2*)(prow + c))[0] = __floats2half2_rn(vals[0] * inv, vals[1] * inv);
    ((__half2*)(prow + c))[1] = __floats2half2_rn(vals[2] * inv, vals[3] * inv);
}

__global__ __launch_bounds__(256) void k_ln(
    const float* __restrict__ X, const float* __restrict__ gamma,
    const float* __restrict__ beta, float* __restrict__ Y)
{
    const int r = blockIdx.x;
    const float* x = X + (size_t)r * DMODEL;
    const int tid = threadIdx.x;
    float v0 = x[tid];
    float v1 = x[tid + 256];
    float s  = v0 + v1;
    float ss = v0 * v0 + v1 * v1;

    __shared__ float shs[8];
    __shared__ float shss[8];
#pragma unroll
    for (int off = 16; off; off >>= 1) {
        s  += __shfl_xor_sync(0xffffffffu, s,  off);
        ss += __shfl_xor_sync(0xffffffffu, ss, off);
    }
    if ((tid & 31) == 0) { shs[tid >> 5] = s; shss[tid >> 5] = ss; }
    __syncthreads();
    s = 0.0f; ss = 0.0f;
#pragma unroll
    for (int w = 0; w < 8; w++) { s += shs[w]; ss += shss[w]; }

    const float mean = s * (1.0f / 512.0f);
    const float var  = ss * (1.0f / 512.0f) - mean * mean;
    const float rstd = rsqrtf(var + 1e-5f);

    Y[(size_t)r * DMODEL + tid]       = (v0 - mean) * rstd * gamma[tid]       + beta[tid];
    Y[(size_t)r * DMODEL + tid + 256] = (v1 - mean) * rstd * gamma[tid + 256] + beta[tid + 256];
}

// ---------------- launch --------------------------
#define GSMEM256 (NSTG * (16384 + 256 * 128))   // 147456
#define GSMEM128 (NSTG * (16384 + 128 * 128))   // 98304

extern "C" void kernel_launch(void* const* d_in, const int* in_sizes, int n_in,
                              void* d_out, int out_size)
{
    const float* q     = (const float*)d_in[0];
    const float* k     = (const float*)d_in[1];
    const float* v     = (const float*)d_in[2];
    const float* Wq    = (const float*)d_in[3];
    const float* Wk    = (const float*)d_in[4];
    const float* Wv    = (const float*)d_in[5];
    const float* Wo    = (const float*)d_in[6];
    const float* gamma = (const float*)d_in[7];
    const float* beta  = (const float*)d_in[8];
    const unsigned char* mask = (const unsigned char*)d_in[9];
    float* out = (float*)d_out;

    __half *q16, *k16, *v16, *wqt, *wkt, *wvt, *wot;
    __half *qh, *kh, *vh, *vht, *sc, *pr, *ao;
    float *og;
    cudaGetSymbolAddress((void**)&q16, g_q16);
    cudaGetSymbolAddress((void**)&k16, g_k16);
    cudaGetSymbolAddress((void**)&v16, g_v16);
    cudaGetSymbolAddress((void**)&wqt, g_wqt16);
    cudaGetSymbolAddress((void**)&wkt, g_wkt16);
    cudaGetSymbolAddress((void**)&wvt, g_wvt16);
    cudaGetSymbolAddress((void**)&wot, g_wot16);
    cudaGetSymbolAddress((void**)&qh,  g_qh16);
    cudaGetSymbolAddress((void**)&kh,  g_kh16);
    cudaGetSymbolAddress((void**)&vh,  g_vh16);
    cudaGetSymbolAddress((void**)&vht, g_vht16);
    cudaGetSymbolAddress((void**)&sc,  g_sc16);
    cudaGetSymbolAddress((void**)&pr,  g_pr16);
    cudaGetSymbolAddress((void**)&ao,  g_ao16);
    cudaGetSymbolAddress((void**)&og,  g_og);

    cudaFuncSetAttribute((k_gemm_h<__half, 256>), cudaFuncAttributeMaxDynamicSharedMemorySize, GSMEM256);
    cudaFuncSetAttribute((k_gemm_h<float, 128>),  cudaFuncAttributeMaxDynamicSharedMemorySize, GSMEM128);

    // fp32 -> fp16 converts
    k_f2h<<<4096, 256>>>(q, q16);
    k_f2h<<<4096, 256>>>(k, k16);
    k_f2h<<<4096, 256>>>(v, v16);

    // transposed fp16 weights
    const dim3 tb(32, 8);
    k_wtrans_h<<<dim3(HDH / 32, DMODEL / 32), tb>>>(Wq, wqt, DMODEL, HDH);
    k_wtrans_h<<<dim3(HDH / 32, DMODEL / 32), tb>>>(Wk, wkt, DMODEL, HDH);
    k_wtrans_h<<<dim3(HDH / 32, DMODEL / 32), tb>>>(Wv, wvt, DMODEL, HDH);
    k_wtrans_h<<<dim3(DMODEL / 32, HDH / 32), tb>>>(Wo, wot, HDH, DMODEL);

    // QKV projections: [8192,512] x [4096,512]^T
    k_gemm_h<__half, 256><<<dim3(HDH / 256, ROWS / 128, 1), 512, GSMEM256>>>(
        q16, DMODEL, 0, 0, wqt, DMODEL, 0, 0, qh, HDH, 0, 0, DMODEL, 1.0f);
    k_gemm_h<__half, 256><<<dim3(HDH / 256, ROWS / 128, 1), 512, GSMEM256>>>(
        k16, DMODEL, 0, 0, wkt, DMODEL, 0, 0, kh, HDH, 0, 0, DMODEL, 1.0f);
    k_gemm_h<__half, 256><<<dim3(HDH / 256, ROWS / 128, 1), 512, GSMEM256>>>(
        v16, DMODEL, 0, 0, wvt, DMODEL, 0, 0, vh, HDH, 0, 0, DMODEL, 1.0f);

    // V transpose per (h,b)
    k_vtrans<<<dim3(16, 32, NHB), tb>>>(vh, vht);

    // scores = Q K^T / sqrt(512) -> fp16
    const float inv_temp = 1.0f / sqrtf(512.0f);
    k_gemm_h<__half, 256><<<dim3(SEQ / 256, SEQ / 128, NHB), 512, GSMEM256>>>(
        qh, HDH, 512, (size_t)SEQ * HDH,
        kh, HDH, 512, (size_t)SEQ * HDH,
        sc, SEQ, (size_t)8 * SEQ * SEQ, (size_t)SEQ * SEQ,
        DMODEL, inv_temp);

    // softmax -> fp16 probs
    k_softmax<<<NHB * SEQ, 256>>>(sc, mask, pr);

    // PV
    k_gemm_h<__half, 256><<<dim3(512 / 256, SEQ / 128, NHB), 512, GSMEM256>>>(
        pr, SEQ, (size_t)8 * SEQ * SEQ, (size_t)SEQ * SEQ,
        vht, SEQ, (size_t)8 * 512 * SEQ, (size_t)512 * SEQ,
        ao, HDH, 512, (size_t)SEQ * HDH,
        SEQ, 1.0f);

    // O projection (TN=128 keeps 256 CTAs for grid fill)
    k_gemm_h<float, 128><<<dim3(DMODEL / 128, ROWS / 128, 1), 256, GSMEM128>>>(
        ao, HDH, 0, 0, wot, HDH, 0, 0, og, DMODEL, 0, 0, HDH, 1.0f);

    // LayerNorm
    k_ln<<<ROWS, 256>>>(og, gamma, beta, out);
}

// round 9
// speedup vs baseline: 1.1340x; 1.1340x over previous
#include <cuda_runtime.h>
#include <cuda_fp16.h>
#include <math.h>
#include <stdint.h>

// ---------------- sizes (fixed) ----------------
#define ROWS   8192
#define DMODEL 512
#define HDH    4096
#define SEQ    1024
#define NHB    64

// ---------------- scratch ----------------------
static __device__ __half g_q16[4194304];    // [8192, 512]
static __device__ __half g_k16[4194304];
static __device__ __half g_v16[4194304];
static __device__ __half g_wqt16[2097152];  // [4096, 512]  W^T
static __device__ __half g_wkt16[2097152];
static __device__ __half g_wvt16[2097152];
static __device__ __half g_wot16[2097152];  // [512, 4096]
static __device__ __half g_qh16[33554432];  // [8192, 4096]
static __device__ __half g_kh16[33554432];
static __device__ __half g_vht16[33554432]; // [64][512][1024]  V^T per (h,b)
static __device__ __half g_pr16[67108864];  // [64, 1024, 1024] exp(scores) fp16
static __device__ float  g_rs[65536];       // [64, 1024] row sums
static __device__ __half g_ao16[33554432];  // [8192, 4096]
static __device__ float  g_og[4194304];     // [8192, 512]

// ---------------- helpers ----------------------
__device__ __forceinline__ uint32_t smem_u32(const void* p) {
    uint32_t a;
    asm("{ .reg .u64 t; cvta.to.shared.u64 t, %1; cvt.u32.u64 %0, t; }" : "=r"(a) : "l"(p));
    return a;
}
__device__ __forceinline__ void mma16816(
    float& c0, float& c1, float& c2, float& c3,
    uint32_t a0, uint32_t a1, uint32_t a2, uint32_t a3,
    uint32_t b0, uint32_t b1)
{
    asm volatile(
        "mma.sync.aligned.m16n8k16.row.col.f32.f16.f16.f32 "
        "{%0,%1,%2,%3}, {%4,%5,%6,%7}, {%8,%9}, {%0,%1,%2,%3};"
        : "+f"(c0), "+f"(c1), "+f"(c2), "+f"(c3)
        : "r"(a0), "r"(a1), "r"(a2), "r"(a3), "r"(b0), "r"(b1));
}
#define LDSM4(r, a) \
    asm volatile("ldmatrix.sync.aligned.m8n8.x4.shared.b16 {%0,%1,%2,%3}, [%4];" \
                 : "=r"((r)[0]), "=r"((r)[1]), "=r"((r)[2]), "=r"((r)[3]) : "r"(a))

// ---------------- fp16 tensor-core GEMM (R5/R7 proven config) ----------------
// C[m,n] = alpha * sum_k A[m,k] * B[n,k]   (both operands K-major fp16)
// CTA 128x128, BK=64 (128B swizzled rows), 3-stage cp.async, 256 thr,
// 8 warps (2x4), warp tile 64x32, 2 CTAs/SM.
// EPI: 0 = plain store (CT fp16 or fp32)
//      1 = mask + exp + fp16 store + per-row sum atomics (scores -> probs)
//      2 = scale rows by 1/rowsum (PV normalization)
#define ABYTES 16384
#define STAGEB 32768
#define NSTG   3
#define GSMEM  (NSTG * STAGEB)          // 98304 B

template <typename CT, int EPI>
__global__ __launch_bounds__(256, 2)
void k_gemm_h(
    const __half* __restrict__ A, int lda, size_t Az1, size_t Az2,
    const __half* __restrict__ B, int ldb, size_t Bz1, size_t Bz2,
    CT* __restrict__ C, int ldc, size_t Cz1, size_t Cz2,
    int K, float alpha,
    const unsigned char* __restrict__ msk, float* __restrict__ rs)
{
    extern __shared__ __align__(128) char dyn[];

    const int z1 = blockIdx.z >> 3, z2 = blockIdx.z & 7;
    A += z1 * Az1 + z2 * Az2 + (size_t)blockIdx.y * 128 * lda;
    B += z1 * Bz1 + z2 * Bz2 + (size_t)blockIdx.x * 128 * ldb;
    C += z1 * Cz1 + z2 * Cz2 + (size_t)blockIdx.y * 128 * ldc + (size_t)blockIdx.x * 128;

    const int tid  = threadIdx.x;
    const int warp = tid >> 5;
    const int lane = tid & 31;
    const int g    = lane >> 2;
    const int tg   = lane & 3;
    const int wm   = (warp >> 2) * 64;
    const int wn   = (warp & 3) * 32;
    const int lr   = tid >> 3;
    const int c8   = tid & 7;

    const int la = lane & 15, ha = lane >> 4;
    const int lb = ((lane >> 4) << 3) | (lane & 7);
    const int hb = (lane >> 3) & 1;

    const uint32_t sb = smem_u32(dyn);

    float acc[4][4][4];
#pragma unroll
    for (int mi = 0; mi < 4; mi++)
#pragma unroll
        for (int ni = 0; ni < 4; ni++)
#pragma unroll
            for (int r = 0; r < 4; r++) acc[mi][ni][r] = 0.0f;

    auto issue = [&](int kc, int st) {
        const int k0 = kc << 6;
        const uint32_t sA = sb + st * STAGEB;
        const uint32_t sB = sA + ABYTES;
#pragma unroll
        for (int i = 0; i < 4; i++) {
            const int r = lr + 32 * i;
            const uint32_t d = sA + r * 128 + ((c8 ^ (r & 7)) << 4);
            const void* s = &A[(size_t)r * lda + k0 + c8 * 8];
            asm volatile("cp.async.cg.shared.global [%0], [%1], 16;" :: "r"(d), "l"(s));
        }
#pragma unroll
        for (int i = 0; i < 4; i++) {
            const int r = lr + 32 * i;
            const uint32_t d = sB + r * 128 + ((c8 ^ (r & 7)) << 4);
            const void* s = &B[(size_t)r * ldb + k0 + c8 * 8];
            asm volatile("cp.async.cg.shared.global [%0], [%1], 16;" :: "r"(d), "l"(s));
        }
        asm volatile("cp.async.commit_group;" ::: "memory");
    };

    auto compute = [&](int st) {
        const uint32_t sA = sb + st * STAGEB;
        const uint32_t sB = sA + ABYTES;
#pragma unroll
        for (int ks = 0; ks < 4; ks++) {
            uint32_t af[4][4], bf[2][4];
#pragma unroll
            for (int mi = 0; mi < 4; mi++) {
                const int rr = wm + mi * 16 + la;
                const int cc = ks * 2 + ha;
                LDSM4(af[mi], sA + rr * 128 + ((cc ^ (rr & 7)) << 4));
            }
#pragma unroll
            for (int np = 0; np < 2; np++) {
                const int rr = wn + np * 16 + lb;
                const int cc = ks * 2 + hb;
                LDSM4(bf[np], sB + rr * 128 + ((cc ^ (rr & 7)) << 4));
            }
#pragma unroll
            for (int mi = 0; mi < 4; mi++)
#pragma unroll
                for (int ni = 0; ni < 4; ni++) {
                    const int np = ni >> 1, o = (ni & 1) * 2;
                    mma16816(acc[mi][ni][0], acc[mi][ni][1], acc[mi][ni][2], acc[mi][ni][3],
                             af[mi][0], af[mi][1], af[mi][2], af[mi][3],
                             bf[np][o], bf[np][o + 1]);
                }
        }
    };

    const int NK = K >> 6;
    issue(0, 0);
    issue(1, 1);
    for (int kc = 0; kc < NK; kc++) {
        if (kc < NK - 1)
            asm volatile("cp.async.wait_group 1;" ::: "memory");
        else
            asm volatile("cp.async.wait_group 0;" ::: "memory");
        __syncthreads();
        if (kc + 2 < NK) issue(kc + 2, (kc + 2) % NSTG);
        compute(kc % NSTG);
    }

    // ---------------- epilogues ----------------
    if constexpr (EPI == 0) {
#pragma unroll
        for (int mi = 0; mi < 4; mi++) {
            const int r = wm + mi * 16 + g;
#pragma unroll
            for (int ni = 0; ni < 4; ni++) {
                const int c = wn + ni * 8 + tg * 2;
                if constexpr (sizeof(CT) == 2) {
                    *(__half2*)&C[(size_t)r * ldc + c] =
                        __floats2half2_rn(alpha * acc[mi][ni][0], alpha * acc[mi][ni][1]);
                    *(__half2*)&C[(size_t)(r + 8) * ldc + c] =
                        __floats2half2_rn(alpha * acc[mi][ni][2], alpha * acc[mi][ni][3]);
                } else {
                    *(float2*)&C[(size_t)r * ldc + c] =
                        make_float2(alpha * acc[mi][ni][0], alpha * acc[mi][ni][1]);
                    *(float2*)&C[(size_t)(r + 8) * ldc + c] =
                        make_float2(alpha * acc[mi][ni][2], alpha * acc[mi][ni][3]);
                }
            }
        }
    } else if constexpr (EPI == 1) {
        // mask + exp + store fp16 exp-matrix + row-sum atomics
        __syncthreads();                       // safe to reuse dyn smem
        float* srs = (float*)dyn;
        for (int i = tid; i < 128; i += 256) srs[i] = 0.0f;
        __syncthreads();
        const int q0  = blockIdx.y * 128;
        const int k0v = blockIdx.x * 128;
        const unsigned char* mbase =
            msk + ((size_t)(z2 * 1024 + q0) * 1024 + k0v);
#pragma unroll
        for (int mi = 0; mi < 4; mi++) {
            const int r = wm + mi * 16 + g;
            float rs0 = 0.0f, rs1 = 0.0f;
#pragma unroll
            for (int ni = 0; ni < 4; ni++) {
                const int c = wn + ni * 8 + tg * 2;
                const unsigned char* m0 = mbase + (size_t)r * 1024 + c;
                const unsigned char* m1 = m0 + (size_t)8 * 1024;
                float e0 = m0[0] ? 0.0f : __expf(alpha * acc[mi][ni][0]);
                float e1 = m0[1] ? 0.0f : __expf(alpha * acc[mi][ni][1]);
                float e2 = m1[0] ? 0.0f : __expf(alpha * acc[mi][ni][2]);
                float e3 = m1[1] ? 0.0f : __expf(alpha * acc[mi][ni][3]);
                *(__half2*)&C[(size_t)r * ldc + c]       = __floats2half2_rn(e0, e1);
                *(__half2*)&C[(size_t)(r + 8) * ldc + c] = __floats2half2_rn(e2, e3);
                rs0 += e0 + e1;
                rs1 += e2 + e3;
            }
            rs0 += __shfl_xor_sync(0xffffffffu, rs0, 1);
            rs0 += __shfl_xor_sync(0xffffffffu, rs0, 2);
            rs1 += __shfl_xor_sync(0xffffffffu, rs1, 1);
            rs1 += __shfl_xor_sync(0xffffffffu, rs1, 2);
            if (tg == 0) {
                atomicAdd(&srs[wm + mi * 16 + g], rs0);
                atomicAdd(&srs[wm + mi * 16 + g + 8], rs1);
            }
        }
        __syncthreads();
        if (tid < 128)
            atomicAdd(&rs[(size_t)blockIdx.z * 1024 + blockIdx.y * 128 + tid], srs[tid]);
    } else {
        // EPI == 2: normalize rows by 1/rowsum
        const float* rsb = rs + (size_t)blockIdx.z * 1024 + blockIdx.y * 128;
#pragma unroll
        for (int mi = 0; mi < 4; mi++) {
            const int r = wm + mi * 16 + g;
            const float inv0 = 1.0f / rsb[r];
            const float inv1 = 1.0f / rsb[r + 8];
#pragma unroll
            for (int ni = 0; ni < 4; ni++) {
                const int c = wn + ni * 8 + tg * 2;
                *(__half2*)&C[(size_t)r * ldc + c] =
                    __floats2half2_rn(inv0 * acc[mi][ni][0], inv0 * acc[mi][ni][1]);
                *(__half2*)&C[(size_t)(r + 8) * ldc + c] =
                    __floats2half2_rn(inv1 * acc[mi][ni][2], inv1 * acc[mi][ni][3]);
            }
        }
    }
}

// ---------------- converts / transposes ----------
__global__ __launch_bounds__(256) void k_f2h(
    const float* __restrict__ in, __half* __restrict__ out)
{
    const int i = (blockIdx.x * 256 + threadIdx.x) * 4;
    float4 v = *(const float4*)&in[i];
    ((__half2*)(out + i))[0] = __floats2half2_rn(v.x, v.y);
    ((__half2*)(out + i))[1] = __floats2half2_rn(v.z, v.w);
}

__global__ __launch_bounds__(256) void k_zero_f(float* __restrict__ p)
{
    p[blockIdx.x * 256 + threadIdx.x] = 0.0f;
}

// out[C][R] = in[R][C]^T, fp32 -> fp16.  grid(C/32, R/32), block(32,8)
__global__ void k_wtrans_h(const float* __restrict__ in, __half* __restrict__ out,
                           int R, int C)
{
    __shared__ float t[32][33];
    const int c0 = blockIdx.x * 32, r0 = blockIdx.y * 32;
    const int tx = threadIdx.x, ty = threadIdx.y;
#pragma unroll
    for (int i = 0; i < 32; i += 8)
        t[ty + i][tx] = in[(size_t)(r0 + ty + i) * C + c0 + tx];
    __syncthreads();
#pragma unroll
    for (int i = 0; i < 32; i += 8)
        out[(size_t)(c0 + ty + i) * R + r0 + tx] = __float2half(t[tx][ty + i]);
}

// ---------------- layernorm -----------------------
__global__ __launch_bounds__(256) void k_ln(
    const float* __restrict__ X, const float* __restrict__ gamma,
    const float* __restrict__ beta, float* __restrict__ Y)
{
    const int r = blockIdx.x;
    const float* x = X + (size_t)r * DMODEL;
    const int tid = threadIdx.x;
    float v0 = x[tid];
    float v1 = x[tid + 256];
    float s  = v0 + v1;
    float ss = v0 * v0 + v1 * v1;

    __shared__ float shs[8];
    __shared__ float shss[8];
#pragma unroll
    for (int off = 16; off; off >>= 1) {
        s  += __shfl_xor_sync(0xffffffffu, s,  off);
        ss += __shfl_xor_sync(0xffffffffu, ss, off);
    }
    if ((tid & 31) == 0) { shs[tid >> 5] = s; shss[tid >> 5] = ss; }
    __syncthreads();
    s = 0.0f; ss = 0.0f;
#pragma unroll
    for (int w = 0; w < 8; w++) { s += shs[w]; ss += shss[w]; }

    const float mean = s * (1.0f / 512.0f);
    const float var  = ss * (1.0f / 512.0f) - mean * mean;
    const float rstd = rsqrtf(var + 1e-5f);

    Y[(size_t)r * DMODEL + tid]       = (v0 - mean) * rstd * gamma[tid]       + beta[tid];
    Y[(size_t)r * DMODEL + tid + 256] = (v1 - mean) * rstd * gamma[tid + 256] + beta[tid + 256];
}

// ---------------- launch --------------------------
extern "C" void kernel_launch(void* const* d_in, const int* in_sizes, int n_in,
                              void* d_out, int out_size)
{
    const float* q     = (const float*)d_in[0];
    const float* k     = (const float*)d_in[1];
    const float* v     = (const float*)d_in[2];
    const float* Wq    = (const float*)d_in[3];
    const float* Wk    = (const float*)d_in[4];
    const float* Wv    = (const float*)d_in[5];
    const float* Wo    = (const float*)d_in[6];
    const float* gamma = (const float*)d_in[7];
    const float* beta  = (const float*)d_in[8];
    const unsigned char* mask = (const unsigned char*)d_in[9];
    float* out = (float*)d_out;

    __half *q16, *k16, *v16, *wqt, *wkt, *wvt, *wot;
    __half *qh, *kh, *vht, *pr, *ao;
    float *og, *rs;
    cudaGetSymbolAddress((void**)&q16, g_q16);
    cudaGetSymbolAddress((void**)&k16, g_k16);
    cudaGetSymbolAddress((void**)&v16, g_v16);
    cudaGetSymbolAddress((void**)&wqt, g_wqt16);
    cudaGetSymbolAddress((void**)&wkt, g_wkt16);
    cudaGetSymbolAddress((void**)&wvt, g_wvt16);
    cudaGetSymbolAddress((void**)&wot, g_wot16);
    cudaGetSymbolAddress((void**)&qh,  g_qh16);
    cudaGetSymbolAddress((void**)&kh,  g_kh16);
    cudaGetSymbolAddress((void**)&vht, g_vht16);
    cudaGetSymbolAddress((void**)&pr,  g_pr16);
    cudaGetSymbolAddress((void**)&ao,  g_ao16);
    cudaGetSymbolAddress((void**)&og,  g_og);
    cudaGetSymbolAddress((void**)&rs,  g_rs);

    cudaFuncSetAttribute((k_gemm_h<__half, 0>), cudaFuncAttributeMaxDynamicSharedMemorySize, GSMEM);
    cudaFuncSetAttribute((k_gemm_h<__half, 1>), cudaFuncAttributeMaxDynamicSharedMemorySize, GSMEM);
    cudaFuncSetAttribute((k_gemm_h<__half, 2>), cudaFuncAttributeMaxDynamicSharedMemorySize, GSMEM);
    cudaFuncSetAttribute((k_gemm_h<float, 0>),  cudaFuncAttributeMaxDynamicSharedMemorySize, GSMEM);

    // fp32 -> fp16 converts
    k_f2h<<<4096, 256>>>(q, q16);
    k_f2h<<<4096, 256>>>(k, k16);
    k_f2h<<<4096, 256>>>(v, v16);

    // transposed fp16 weights
    const dim3 tb(32, 8);
    k_wtrans_h<<<dim3(HDH / 32, DMODEL / 32), tb>>>(Wq, wqt, DMODEL, HDH);
    k_wtrans_h<<<dim3(HDH / 32, DMODEL / 32), tb>>>(Wk, wkt, DMODEL, HDH);
    k_wtrans_h<<<dim3(HDH / 32, DMODEL / 32), tb>>>(Wv, wvt, DMODEL, HDH);
    k_wtrans_h<<<dim3(DMODEL / 32, HDH / 32), tb>>>(Wo, wot, HDH, DMODEL);

    // zero rowsums (accumulated by scores epilogue)
    k_zero_f<<<256, 256>>>(rs);

    // Q, K projections: [8192,512] x [4096,512]^T
    k_gemm_h<__half, 0><<<dim3(HDH / 128, ROWS / 128, 1), 256, GSMEM>>>(
        q16, DMODEL, 0, 0, wqt, DMODEL, 0, 0, qh, HDH, 0, 0, DMODEL, 1.0f,
        nullptr, nullptr);
    k_gemm_h<__half, 0><<<dim3(HDH / 128, ROWS / 128, 1), 256, GSMEM>>>(
        k16, DMODEL, 0, 0, wkt, DMODEL, 0, 0, kh, HDH, 0, 0, DMODEL, 1.0f,
        nullptr, nullptr);

    // V projection transposed: vht[h,b][d][s] = sum_k WvT[h*512+d,k] * v16[b*1024+s,k]
    k_gemm_h<__half, 0><<<dim3(SEQ / 128, 512 / 128, NHB), 256, GSMEM>>>(
        wvt, DMODEL, (size_t)512 * DMODEL, 0,
        v16, DMODEL, 0, (size_t)SEQ * DMODEL,
        vht, SEQ, (size_t)8 * 512 * SEQ, (size_t)512 * SEQ,
        DMODEL, 1.0f, nullptr, nullptr);

    // scores -> masked exp fp16 (pr) + row sums, fused
    const float inv_temp = 1.0f / sqrtf(512.0f);
    k_gemm_h<__half, 1><<<dim3(SEQ / 128, SEQ / 128, NHB), 256, GSMEM>>>(
        qh, HDH, 512, (size_t)SEQ * HDH,
        kh, HDH, 512, (size_t)SEQ * HDH,
        pr, SEQ, (size_t)8 * SEQ * SEQ, (size_t)SEQ * SEQ,
        DMODEL, inv_temp, mask, rs);

    // PV with fused 1/rowsum normalization
    k_gemm_h<__half, 2><<<dim3(512 / 128, SEQ / 128, NHB), 256, GSMEM>>>(
        pr, SEQ, (size_t)8 * SEQ * SEQ, (size_t)SEQ * SEQ,
        vht, SEQ, (size_t)8 * 512 * SEQ, (size_t)512 * SEQ,
        ao, HDH, 512, (size_t)SEQ * HDH,
        SEQ, 1.0f, nullptr, rs);

    // O projection
    k_gemm_h<float, 0><<<dim3(DMODEL / 128, ROWS / 128, 1), 256, GSMEM>>>(
        ao, HDH, 0, 0, wot, HDH, 0, 0, og, DMODEL, 0, 0, HDH, 1.0f,
        nullptr, nullptr);

    // LayerNorm
    k_ln<<<ROWS, 256>>>(og, gamma, beta, out);
}

// round 12
// speedup vs baseline: 1.1421x; 1.0072x over previous
#include <cuda_runtime.h>
#include <cuda_fp16.h>
#include <math.h>
#include <stdint.h>

// ---------------- sizes (fixed) ----------------
#define ROWS   8192
#define DMODEL 512
#define HDH    4096
#define SEQ    1024
#define NHB    64

// ---------------- scratch ----------------------
static __device__ __half g_q16[4194304];    // [8192, 512]
static __device__ __half g_k16[4194304];
static __device__ __half g_v16[4194304];
static __device__ __half g_wqt16[2097152];  // [4096, 512]  W^T
static __device__ __half g_wkt16[2097152];
static __device__ __half g_wvt16[2097152];
static __device__ __half g_wot16[2097152];  // [512, 4096]
static __device__ __half g_qh16[33554432];  // [8192, 4096]
static __device__ __half g_kh16[33554432];
static __device__ __half g_vht16[33554432]; // [64][512][1024]  V^T per (h,b)
static __device__ __half g_pr16[67108864];  // [64, 1024, 1024] exp(scores) fp16
static __device__ float  g_rs[65536];       // [64, 1024] row sums
static __device__ __half g_ao16[33554432];  // [8192, 4096]
static __device__ float  g_og[4194304];     // [8192, 512]

// ---------------- helpers ----------------------
__device__ __forceinline__ uint32_t smem_u32(const void* p) {
    uint32_t a;
    asm("{ .reg .u64 t; cvta.to.shared.u64 t, %1; cvt.u32.u64 %0, t; }" : "=r"(a) : "l"(p));
    return a;
}
__device__ __forceinline__ void mma16816(
    float& c0, float& c1, float& c2, float& c3,
    uint32_t a0, uint32_t a1, uint32_t a2, uint32_t a3,
    uint32_t b0, uint32_t b1)
{
    asm volatile(
        "mma.sync.aligned.m16n8k16.row.col.f32.f16.f16.f32 "
        "{%0,%1,%2,%3}, {%4,%5,%6,%7}, {%8,%9}, {%0,%1,%2,%3};"
        : "+f"(c0), "+f"(c1), "+f"(c2), "+f"(c3)
        : "r"(a0), "r"(a1), "r"(a2), "r"(a3), "r"(b0), "r"(b1));
}
#define LDSM4(r, a) \
    asm volatile("ldmatrix.sync.aligned.m8n8.x4.shared.b16 {%0,%1,%2,%3}, [%4];" \
                 : "=r"((r)[0]), "=r"((r)[1]), "=r"((r)[2]), "=r"((r)[3]) : "r"(a))

// ---------------- fp16 tensor-core GEMM (proven config — DO NOT TOUCH) ------
// C[m,n] = alpha * sum_k A[m,k] * B[n,k]   (both operands K-major fp16)
// CTA 128x128, BK=64 (128B swizzled rows), 3-stage cp.async, 256 thr,
// 8 warps (2x4), warp tile 64x32, 2 CTAs/SM.
// EPI: 0 = plain store; 1 = mask+exp+rowsum atomics; 2 = 1/rowsum scaling.
#define ABYTES 16384
#define STAGEB 32768
#define NSTG   3
#define GSMEM  (NSTG * STAGEB)          // 98304 B

template <typename CT, int EPI>
__global__ __launch_bounds__(256, 2)
void k_gemm_h(
    const __half* __restrict__ A, int lda, size_t Az1, size_t Az2,
    const __half* __restrict__ B, int ldb, size_t Bz1, size_t Bz2,
    CT* __restrict__ C, int ldc, size_t Cz1, size_t Cz2,
    int K, float alpha,
    const unsigned char* __restrict__ msk, float* __restrict__ rs)
{
    extern __shared__ __align__(128) char dyn[];

    const int z1 = blockIdx.z >> 3, z2 = blockIdx.z & 7;
    A += z1 * Az1 + z2 * Az2 + (size_t)blockIdx.y * 128 * lda;
    B += z1 * Bz1 + z2 * Bz2 + (size_t)blockIdx.x * 128 * ldb;
    C += z1 * Cz1 + z2 * Cz2 + (size_t)blockIdx.y * 128 * ldc + (size_t)blockIdx.x * 128;

    const int tid  = threadIdx.x;
    const int warp = tid >> 5;
    const int lane = tid & 31;
    const int g    = lane >> 2;
    const int tg   = lane & 3;
    const int wm   = (warp >> 2) * 64;
    const int wn   = (warp & 3) * 32;
    const int lr   = tid >> 3;
    const int c8   = tid & 7;

    const int la = lane & 15, ha = lane >> 4;
    const int lb = ((lane >> 4) << 3) | (lane & 7);
    const int hb = (lane >> 3) & 1;

    const uint32_t sb = smem_u32(dyn);

    float acc[4][4][4];
#pragma unroll
    for (int mi = 0; mi < 4; mi++)
#pragma unroll
        for (int ni = 0; ni < 4; ni++)
#pragma unroll
            for (int r = 0; r < 4; r++) acc[mi][ni][r] = 0.0f;

    auto issue = [&](int kc, int st) {
        const int k0 = kc << 6;
        const uint32_t sA = sb + st * STAGEB;
        const uint32_t sB = sA + ABYTES;
#pragma unroll
        for (int i = 0; i < 4; i++) {
            const int r = lr + 32 * i;
            const uint32_t d = sA + r * 128 + ((c8 ^ (r & 7)) << 4);
            const void* s = &A[(size_t)r * lda + k0 + c8 * 8];
            asm volatile("cp.async.cg.shared.global [%0], [%1], 16;" :: "r"(d), "l"(s));
        }
#pragma unroll
        for (int i = 0; i < 4; i++) {
            const int r = lr + 32 * i;
            const uint32_t d = sB + r * 128 + ((c8 ^ (r & 7)) << 4);
            const void* s = &B[(size_t)r * ldb + k0 + c8 * 8];
            asm volatile("cp.async.cg.shared.global [%0], [%1], 16;" :: "r"(d), "l"(s));
        }
        asm volatile("cp.async.commit_group;" ::: "memory");
    };

    auto compute = [&](int st) {
        const uint32_t sA = sb + st * STAGEB;
        const uint32_t sB = sA + ABYTES;
#pragma unroll
        for (int ks = 0; ks < 4; ks++) {
            uint32_t af[4][4], bf[2][4];
#pragma unroll
            for (int mi = 0; mi < 4; mi++) {
                const int rr = wm + mi * 16 + la;
                const int cc = ks * 2 + ha;
                LDSM4(af[mi], sA + rr * 128 + ((cc ^ (rr & 7)) << 4));
            }
#pragma unroll
            for (int np = 0; np < 2; np++) {
                const int rr = wn + np * 16 + lb;
                const int cc = ks * 2 + hb;
                LDSM4(bf[np], sB + rr * 128 + ((cc ^ (rr & 7)) << 4));
            }
#pragma unroll
            for (int mi = 0; mi < 4; mi++)
#pragma unroll
                for (int ni = 0; ni < 4; ni++) {
                    const int np = ni >> 1, o = (ni & 1) * 2;
                    mma16816(acc[mi][ni][0], acc[mi][ni][1], acc[mi][ni][2], acc[mi][ni][3],
                             af[mi][0], af[mi][1], af[mi][2], af[mi][3],
                             bf[np][o], bf[np][o + 1]);
                }
        }
    };

    const int NK = K >> 6;
    issue(0, 0);
    issue(1, 1);
    for (int kc = 0; kc < NK; kc++) {
        if (kc < NK - 1)
            asm volatile("cp.async.wait_group 1;" ::: "memory");
        else
            asm volatile("cp.async.wait_group 0;" ::: "memory");
        __syncthreads();
        if (kc + 2 < NK) issue(kc + 2, (kc + 2) % NSTG);
        compute(kc % NSTG);
    }

    // ---------------- epilogues ----------------
    if constexpr (EPI == 0) {
#pragma unroll
        for (int mi = 0; mi < 4; mi++) {
            const int r = wm + mi * 16 + g;
#pragma unroll
            for (int ni = 0; ni < 4; ni++) {
                const int c = wn + ni * 8 + tg * 2;
                if constexpr (sizeof(CT) == 2) {
                    *(__half2*)&C[(size_t)r * ldc + c] =
                        __floats2half2_rn(alpha * acc[mi][ni][0], alpha * acc[mi][ni][1]);
                    *(__half2*)&C[(size_t)(r + 8) * ldc + c] =
                        __floats2half2_rn(alpha * acc[mi][ni][2], alpha * acc[mi][ni][3]);
                } else {
                    *(float2*)&C[(size_t)r * ldc + c] =
                        make_float2(alpha * acc[mi][ni][0], alpha * acc[mi][ni][1]);
                    *(float2*)&C[(size_t)(r + 8) * ldc + c] =
                        make_float2(alpha * acc[mi][ni][2], alpha * acc[mi][ni][3]);
                }
            }
        }
    } else if constexpr (EPI == 1) {
        __syncthreads();
        float* srs = (float*)dyn;
        for (int i = tid; i < 128; i += 256) srs[i] = 0.0f;
        __syncthreads();
        const int q0  = blockIdx.y * 128;
        const int k0v = blockIdx.x * 128;
        const unsigned char* mbase =
            msk + ((size_t)(z2 * 1024 + q0) * 1024 + k0v);
#pragma unroll
        for (int mi = 0; mi < 4; mi++) {
            const int r = wm + mi * 16 + g;
            float rs0 = 0.0f, rs1 = 0.0f;
#pragma unroll
            for (int ni = 0; ni < 4; ni++) {
                const int c = wn + ni * 8 + tg * 2;
                const unsigned char* m0 = mbase + (size_t)r * 1024 + c;
                const unsigned char* m1 = m0 + (size_t)8 * 1024;
                float e0 = m0[0] ? 0.0f : __expf(alpha * acc[mi][ni][0]);
                float e1 = m0[1] ? 0.0f : __expf(alpha * acc[mi][ni][1]);
                float e2 = m1[0] ? 0.0f : __expf(alpha * acc[mi][ni][2]);
                float e3 = m1[1] ? 0.0f : __expf(alpha * acc[mi][ni][3]);
                *(__half2*)&C[(size_t)r * ldc + c]       = __floats2half2_rn(e0, e1);
                *(__half2*)&C[(size_t)(r + 8) * ldc + c] = __floats2half2_rn(e2, e3);
                rs0 += e0 + e1;
                rs1 += e2 + e3;
            }
            rs0 += __shfl_xor_sync(0xffffffffu, rs0, 1);
            rs0 += __shfl_xor_sync(0xffffffffu, rs0, 2);
            rs1 += __shfl_xor_sync(0xffffffffu, rs1, 1);
            rs1 += __shfl_xor_sync(0xffffffffu, rs1, 2);
            if (tg == 0) {
                atomicAdd(&srs[wm + mi * 16 + g], rs0);
                atomicAdd(&srs[wm + mi * 16 + g + 8], rs1);
            }
        }
        __syncthreads();
        if (tid < 128)
            atomicAdd(&rs[(size_t)blockIdx.z * 1024 + blockIdx.y * 128 + tid], srs[tid]);
    } else {
        const float* rsb = rs + (size_t)blockIdx.z * 1024 + blockIdx.y * 128;
#pragma unroll
        for (int mi = 0; mi < 4; mi++) {
            const int r = wm + mi * 16 + g;
            const float inv0 = 1.0f / rsb[r];
            const float inv1 = 1.0f / rsb[r + 8];
#pragma unroll
            for (int ni = 0; ni < 4; ni++) {
                const int c = wn + ni * 8 + tg * 2;
                *(__half2*)&C[(size_t)r * ldc + c] =
                    __floats2half2_rn(inv0 * acc[mi][ni][0], inv0 * acc[mi][ni][1]);
                *(__half2*)&C[(size_t)(r + 8) * ldc + c] =
                    __floats2half2_rn(inv1 * acc[mi][ni][2], inv1 * acc[mi][ni][3]);
            }
        }
    }
}

// ---------------- merged converts / transposes ----------
// One launch converts q, k, v (blockIdx.y selects the array).
__global__ __launch_bounds__(256) void k_f2h3(
    const float* __restrict__ i0, const float* __restrict__ i1,
    const float* __restrict__ i2,
    __half* __restrict__ o0, __half* __restrict__ o1, __half* __restrict__ o2)
{
    const float* in  = (blockIdx.y == 0) ? i0 : (blockIdx.y == 1) ? i1 : i2;
    __half*      out = (blockIdx.y == 0) ? o0 : (blockIdx.y == 1) ? o1 : o2;
    const int i = (blockIdx.x * 256 + threadIdx.x) * 4;
    float4 v = *(const float4*)&in[i];
    ((__half2*)(out + i))[0] = __floats2half2_rn(v.x, v.y);
    ((__half2*)(out + i))[1] = __floats2half2_rn(v.z, v.w);
}

__global__ __launch_bounds__(256) void k_zero_f(float* __restrict__ p)
{
    p[blockIdx.x * 256 + threadIdx.x] = 0.0f;
}

// Transpose fp32 [R,C] -> fp16 [C,R].  grid(C/32, R/32, nmat), block(32,8).
__global__ void k_wtrans3_h(
    const float* __restrict__ i0, const float* __restrict__ i1,
    const float* __restrict__ i2,
    __half* __restrict__ o0, __half* __restrict__ o1, __half* __restrict__ o2,
    int R, int C)
{
    const float* in  = (blockIdx.z == 0) ? i0 : (blockIdx.z == 1) ? i1 : i2;
    __half*      out = (blockIdx.z == 0) ? o0 : (blockIdx.z == 1) ? o1 : o2;
    __shared__ float t[32][33];
    const int c0 = blockIdx.x * 32, r0 = blockIdx.y * 32;
    const int tx = threadIdx.x, ty = threadIdx.y;
#pragma unroll
    for (int i = 0; i < 32; i += 8)
        t[ty + i][tx] = in[(size_t)(r0 + ty + i) * C + c0 + tx];
    __syncthreads();
#pragma unroll
    for (int i = 0; i < 32; i += 8)
        out[(size_t)(c0 + ty + i) * R + r0 + tx] = __float2half(t[tx][ty + i]);
}

__global__ void k_wtrans_h(const float* __restrict__ in, __half* __restrict__ out,
                           int R, int C)
{
    __shared__ float t[32][33];
    const int c0 = blockIdx.x * 32, r0 = blockIdx.y * 32;
    const int tx = threadIdx.x, ty = threadIdx.y;
#pragma unroll
    for (int i = 0; i < 32; i += 8)
        t[ty + i][tx] = in[(size_t)(r0 + ty + i) * C + c0 + tx];
    __syncthreads();
#pragma unroll
    for (int i = 0; i < 32; i += 8)
        out[(size_t)(c0 + ty + i) * R + r0 + tx] = __float2half(t[tx][ty + i]);
}

// ---------------- layernorm -----------------------
__global__ __launch_bounds__(256) void k_ln(
    const float* __restrict__ X, const float* __restrict__ gamma,
    const float* __restrict__ beta, float* __restrict__ Y)
{
    const int r = blockIdx.x;
    const float* x = X + (size_t)r * DMODEL;
    const int tid = threadIdx.x;
    float v0 = x[tid];
    float v1 = x[tid + 256];
    float s  = v0 + v1;
    float ss = v0 * v0 + v1 * v1;

    __shared__ float shs[8];
    __shared__ float shss[8];
#pragma unroll
    for (int off = 16; off; off >>= 1) {
        s  += __shfl_xor_sync(0xffffffffu, s,  off);
        ss += __shfl_xor_sync(0xffffffffu, ss, off);
    }
    if ((tid & 31) == 0) { shs[tid >> 5] = s; shss[tid >> 5] = ss; }
    __syncthreads();
    s = 0.0f; ss = 0.0f;
#pragma unroll
    for (int w = 0; w < 8; w++) { s += shs[w]; ss += shss[w]; }

    const float mean = s * (1.0f / 512.0f);
    const float var  = ss * (1.0f / 512.0f) - mean * mean;
    const float rstd = rsqrtf(var + 1e-5f);

    Y[(size_t)r * DMODEL + tid]       = (v0 - mean) * rstd * gamma[tid]       + beta[tid];
    Y[(size_t)r * DMODEL + tid + 256] = (v1 - mean) * rstd * gamma[tid + 256] + beta[tid + 256];
}

// ---------------- launch --------------------------
extern "C" void kernel_launch(void* const* d_in, const int* in_sizes, int n_in,
                              void* d_out, int out_size)
{
    const float* q     = (const float*)d_in[0];
    const float* k     = (const float*)d_in[1];
    const float* v     = (const float*)d_in[2];
    const float* Wq    = (const float*)d_in[3];
    const float* Wk    = (const float*)d_in[4];
    const float* Wv    = (const float*)d_in[5];
    const float* Wo    = (const float*)d_in[6];
    const float* gamma = (const float*)d_in[7];
    const float* beta  = (const float*)d_in[8];
    const unsigned char* mask = (const unsigned char*)d_in[9];
    float* out = (float*)d_out;

    __half *q16, *k16, *v16, *wqt, *wkt, *wvt, *wot;
    __half *qh, *kh, *vht, *pr, *ao;
    float *og, *rs;
    cudaGetSymbolAddress((void**)&q16, g_q16);
    cudaGetSymbolAddress((void**)&k16, g_k16);
    cudaGetSymbolAddress((void**)&v16, g_v16);
    cudaGetSymbolAddress((void**)&wqt, g_wqt16);
    cudaGetSymbolAddress((void**)&wkt, g_wkt16);
    cudaGetSymbolAddress((void**)&wvt, g_wvt16);
    cudaGetSymbolAddress((void**)&wot, g_wot16);
    cudaGetSymbolAddress((void**)&qh,  g_qh16);
    cudaGetSymbolAddress((void**)&kh,  g_kh16);
    cudaGetSymbolAddress((void**)&vht, g_vht16);
    cudaGetSymbolAddress((void**)&pr,  g_pr16);
    cudaGetSymbolAddress((void**)&ao,  g_ao16);
    cudaGetSymbolAddress((void**)&og,  g_og);
    cudaGetSymbolAddress((void**)&rs,  g_rs);

    cudaFuncSetAttribute((k_gemm_h<__half, 0>), cudaFuncAttributeMaxDynamicSharedMemorySize, GSMEM);
    cudaFuncSetAttribute((k_gemm_h<__half, 1>), cudaFuncAttributeMaxDynamicSharedMemorySize, GSMEM);
    cudaFuncSetAttribute((k_gemm_h<__half, 2>), cudaFuncAttributeMaxDynamicSharedMemorySize, GSMEM);
    cudaFuncSetAttribute((k_gemm_h<float, 0>),  cudaFuncAttributeMaxDynamicSharedMemorySize, GSMEM);

    // fp32 -> fp16 converts (one launch for q, k, v)
    k_f2h3<<<dim3(4096, 3), 256>>>(q, k, v, q16, k16, v16);

    // transposed fp16 weights (one launch for Wq/Wk/Wv; Wo separate shape)
    const dim3 tb(32, 8);
    k_wtrans3_h<<<dim3(HDH / 32, DMODEL / 32, 3), tb>>>(
        Wq, Wk, Wv, wqt, wkt, wvt, DMODEL, HDH);
    k_wtrans_h<<<dim3(DMODEL / 32, HDH / 32), tb>>>(Wo, wot, HDH, DMODEL);

    // zero rowsums (accumulated by scores epilogue)
    k_zero_f<<<256, 256>>>(rs);

    // Q, K projections: [8192,512] x [4096,512]^T
    k_gemm_h<__half, 0><<<dim3(HDH / 128, ROWS / 128, 1), 256, GSMEM>>>(
        q16, DMODEL, 0, 0, wqt, DMODEL, 0, 0, qh, HDH, 0, 0, DMODEL, 1.0f,
        nullptr, nullptr);
    k_gemm_h<__half, 0><<<dim3(HDH / 128, ROWS / 128, 1), 256, GSMEM>>>(
        k16, DMODEL, 0, 0, wkt, DMODEL, 0, 0, kh, HDH, 0, 0, DMODEL, 1.0f,
        nullptr, nullptr);

    // V projection transposed: vht[h,b][d][s] = sum_k WvT[h*512+d,k] * v16[b*1024+s,k]
    k_gemm_h<__half, 0><<<dim3(SEQ / 128, 512 / 128, NHB), 256, GSMEM>>>(
        wvt, DMODEL, (size_t)512 * DMODEL, 0,
        v16, DMODEL, 0, (size_t)SEQ * DMODEL,
        vht, SEQ, (size_t)8 * 512 * SEQ, (size_t)512 * SEQ,
        DMODEL, 1.0f, nullptr, nullptr);

    // scores -> masked exp fp16 (pr) + row sums, fused
    const float inv_temp = 1.0f / sqrtf(512.0f);
    k_gemm_h<__half, 1><<<dim3(SEQ / 128, SEQ / 128, NHB), 256, GSMEM>>>(
        qh, HDH, 512, (size_t)SEQ * HDH,
        kh, HDH, 512, (size_t)SEQ * HDH,
        pr, SEQ, (size_t)8 * SEQ * SEQ, (size_t)SEQ * SEQ,
        DMODEL, inv_temp, mask, rs);

    // PV with fused 1/rowsum normalization
    k_gemm_h<__half, 2><<<dim3(512 / 128, SEQ / 128, NHB), 256, GSMEM>>>(
        pr, SEQ, (size_t)8 * SEQ * SEQ, (size_t)SEQ * SEQ,
        vht, SEQ, (size_t)8 * 512 * SEQ, (size_t)512 * SEQ,
        ao, HDH, 512, (size_t)SEQ * HDH,
        SEQ, 1.0f, nullptr, rs);

    // O projection
    k_gemm_h<float, 0><<<dim3(DMODEL / 128, ROWS / 128, 1), 256, GSMEM>>>(
        ao, HDH, 0, 0, wot, HDH, 0, 0, og, DMODEL, 0, 0, HDH, 1.0f,
        nullptr, nullptr);

    // LayerNorm
    k_ln<<<ROWS, 256>>>(og, gamma, beta, out);
}

// round 14
// speedup vs baseline: 1.1504x; 1.0072x over previous
#include <cuda_runtime.h>
#include <cuda_fp16.h>
#include <math.h>
#include <stdint.h>

// ---------------- sizes (fixed) ----------------
#define ROWS   8192
#define DMODEL 512
#define HDH    4096
#define SEQ    1024
#define NHB    64

// ---------------- scratch ----------------------
static __device__ __half g_qk16[8388608];   // q16 [8192,512] @0, k16 @4194304
static __device__ __half g_v16[4194304];    // [8192, 512]
static __device__ __half g_wqk16[4194304];  // wqt [4096,512] @0, wkt @2097152
static __device__ __half g_wvt16[2097152];  // [4096, 512]
static __device__ __half g_wot16[2097152];  // [512, 4096]
static __device__ __half g_qkh16[67108864]; // qh [8][8192][512] @0, kh @33554432 (head-separated)
static __device__ __half g_vht16[33554432]; // [64][512][1024]  V^T per (h,b)
static __device__ __half g_pr16[67108864];  // [64, 1024, 1024] exp(scores) fp16
static __device__ float  g_rsp[524288];     // [64][1024][8] row-sum partials
static __device__ __half g_ao16[33554432];  // [8192, 4096]
static __device__ float  g_og[4194304];     // [8192, 512]

// ---------------- helpers ----------------------
__device__ __forceinline__ uint32_t smem_u32(const void* p) {
    uint32_t a;
    asm("{ .reg .u64 t; cvta.to.shared.u64 t, %1; cvt.u32.u64 %0, t; }" : "=r"(a) : "l"(p));
    return a;
}
__device__ __forceinline__ void mma16816(
    float& c0, float& c1, float& c2, float& c3,
    uint32_t a0, uint32_t a1, uint32_t a2, uint32_t a3,
    uint32_t b0, uint32_t b1)
{
    asm volatile(
        "mma.sync.aligned.m16n8k16.row.col.f32.f16.f16.f32 "
        "{%0,%1,%2,%3}, {%4,%5,%6,%7}, {%8,%9}, {%0,%1,%2,%3};"
        : "+f"(c0), "+f"(c1), "+f"(c2), "+f"(c3)
        : "r"(a0), "r"(a1), "r"(a2), "r"(a3), "r"(b0), "r"(b1));
}
#define LDSM4(r, a) \
    asm volatile("ldmatrix.sync.aligned.m8n8.x4.shared.b16 {%0,%1,%2,%3}, [%4];" \
                 : "=r"((r)[0]), "=r"((r)[1]), "=r"((r)[2]), "=r"((r)[3]) : "r"(a))

// ---------------- fp16 tensor-core GEMM (proven config — DO NOT TOUCH) ------
// C[m,n] = alpha * sum_k A[m,k] * B[n,k]   (both operands K-major fp16)
// CTA 128x128, BK=64 (128B swizzled rows), 3-stage cp.async, 256 thr,
// 8 warps (2x4), warp tile 64x32, 2 CTAs/SM.
// EPI: 0 = plain store; 1 = mask+exp+rowsum partial store; 2 = 1/rowsum scale.
#define ABYTES 16384
#define STAGEB 32768
#define NSTG   3
#define GSMEM  (NSTG * STAGEB)          // 98304 B

template <typename CT, int EPI>
__global__ __launch_bounds__(256, 2)
void k_gemm_h(
    const __half* __restrict__ A, int lda, size_t Az1, size_t Az2,
    const __half* __restrict__ B, int ldb, size_t Bz1, size_t Bz2,
    CT* __restrict__ C, int ldc, size_t Cz1, size_t Cz2,
    int K, float alpha,
    const unsigned char* __restrict__ msk, float* __restrict__ rs)
{
    extern __shared__ __align__(128) char dyn[];

    const int z1 = blockIdx.z >> 3, z2 = blockIdx.z & 7;
    A += z1 * Az1 + z2 * Az2 + (size_t)blockIdx.y * 128 * lda;
    B += z1 * Bz1 + z2 * Bz2 + (size_t)blockIdx.x * 128 * ldb;
    C += z1 * Cz1 + z2 * Cz2 + (size_t)blockIdx.y * 128 * ldc + (size_t)blockIdx.x * 128;

    const int tid  = threadIdx.x;
    const int warp = tid >> 5;
    const int lane = tid & 31;
    const int g    = lane >> 2;
    const int tg   = lane & 3;
    const int wm   = (warp >> 2) * 64;
    const int wn   = (warp & 3) * 32;
    const int lr   = tid >> 3;
    const int c8   = tid & 7;

    const int la = lane & 15, ha = lane >> 4;
    const int lb = ((lane >> 4) << 3) | (lane & 7);
    const int hb = (lane >> 3) & 1;

    const uint32_t sb = smem_u32(dyn);

    float acc[4][4][4];
#pragma unroll
    for (int mi = 0; mi < 4; mi++)
#pragma unroll
        for (int ni = 0; ni < 4; ni++)
#pragma unroll
            for (int r = 0; r < 4; r++) acc[mi][ni][r] = 0.0f;

    auto issue = [&](int kc, int st) {
        const int k0 = kc << 6;
        const uint32_t sA = sb + st * STAGEB;
        const uint32_t sB = sA + ABYTES;
#pragma unroll
        for (int i = 0; i < 4; i++) {
            const int r = lr + 32 * i;
            const uint32_t d = sA + r * 128 + ((c8 ^ (r & 7)) << 4);
            const void* s = &A[(size_t)r * lda + k0 + c8 * 8];
            asm volatile("cp.async.cg.shared.global [%0], [%1], 16;" :: "r"(d), "l"(s));
        }
#pragma unroll
        for (int i = 0; i < 4; i++) {
            const int r = lr + 32 * i;
            const uint32_t d = sB + r * 128 + ((c8 ^ (r & 7)) << 4);
            const void* s = &B[(size_t)r * ldb + k0 + c8 * 8];
            asm volatile("cp.async.cg.shared.global [%0], [%1], 16;" :: "r"(d), "l"(s));
        }
        asm volatile("cp.async.commit_group;" ::: "memory");
    };

    auto compute = [&](int st) {
        const uint32_t sA = sb + st * STAGEB;
        const uint32_t sB = sA + ABYTES;
#pragma unroll
        for (int ks = 0; ks < 4; ks++) {
            uint32_t af[4][4], bf[2][4];
#pragma unroll
            for (int mi = 0; mi < 4; mi++) {
                const int rr = wm + mi * 16 + la;
                const int cc = ks * 2 + ha;
                LDSM4(af[mi], sA + rr * 128 + ((cc ^ (rr & 7)) << 4));
            }
#pragma unroll
            for (int np = 0; np < 2; np++) {
                const int rr = wn + np * 16 + lb;
                const int cc = ks * 2 + hb;
                LDSM4(bf[np], sB + rr * 128 + ((cc ^ (rr & 7)) << 4));
            }
#pragma unroll
            for (int mi = 0; mi < 4; mi++)
#pragma unroll
                for (int ni = 0; ni < 4; ni++) {
                    const int np = ni >> 1, o = (ni & 1) * 2;
                    mma16816(acc[mi][ni][0], acc[mi][ni][1], acc[mi][ni][2], acc[mi][ni][3],
                             af[mi][0], af[mi][1], af[mi][2], af[mi][3],
                             bf[np][o], bf[np][o + 1]);
                }
        }
    };

    const int NK = K >> 6;
    issue(0, 0);
    issue(1, 1);
    for (int kc = 0; kc < NK; kc++) {
        if (kc < NK - 1)
            asm volatile("cp.async.wait_group 1;" ::: "memory");
        else
            asm volatile("cp.async.wait_group 0;" ::: "memory");
        __syncthreads();
        if (kc + 2 < NK) issue(kc + 2, (kc + 2) % NSTG);
        compute(kc % NSTG);
    }

    // ---------------- epilogues ----------------
    if constexpr (EPI == 0) {
#pragma unroll
        for (int mi = 0; mi < 4; mi++) {
            const int r = wm + mi * 16 + g;
#pragma unroll
            for (int ni = 0; ni < 4; ni++) {
                const int c = wn + ni * 8 + tg * 2;
                if constexpr (sizeof(CT) == 2) {
                    *(__half2*)&C[(size_t)r * ldc + c] =
                        __floats2half2_rn(alpha * acc[mi][ni][0], alpha * acc[mi][ni][1]);
                    *(__half2*)&C[(size_t)(r + 8) * ldc + c] =
                        __floats2half2_rn(alpha * acc[mi][ni][2], alpha * acc[mi][ni][3]);
                } else {
                    *(float2*)&C[(size_t)r * ldc + c] =
                        make_float2(alpha * acc[mi][ni][0], alpha * acc[mi][ni][1]);
                    *(float2*)&C[(size_t)(r + 8) * ldc + c] =
                        make_float2(alpha * acc[mi][ni][2], alpha * acc[mi][ni][3]);
                }
            }
        }
    } else if constexpr (EPI == 1) {
        // mask + exp + fp16 store; per-x-tile row-sum partial (no atomics)
        __syncthreads();
        float* srs = (float*)dyn;
        for (int i = tid; i < 128; i += 256) srs[i] = 0.0f;
        __syncthreads();
        const int q0  = blockIdx.y * 128;
        const int k0v = blockIdx.x * 128;
        const unsigned char* mbase =
            msk + ((size_t)(z2 * 1024 + q0) * 1024 + k0v);
#pragma unroll
        for (int mi = 0; mi < 4; mi++) {
            const int r = wm + mi * 16 + g;
            float rs0 = 0.0f, rs1 = 0.0f;
#pragma unroll
            for (int ni = 0; ni < 4; ni++) {
                const int c = wn + ni * 8 + tg * 2;
                const unsigned char* m0 = mbase + (size_t)r * 1024 + c;
                const unsigned char* m1 = m0 + (size_t)8 * 1024;
                float e0 = m0[0] ? 0.0f : __expf(alpha * acc[mi][ni][0]);
                float e1 = m0[1] ? 0.0f : __expf(alpha * acc[mi][ni][1]);
                float e2 = m1[0] ? 0.0f : __expf(alpha * acc[mi][ni][2]);
                float e3 = m1[1] ? 0.0f : __expf(alpha * acc[mi][ni][3]);
                *(__half2*)&C[(size_t)r * ldc + c]       = __floats2half2_rn(e0, e1);
                *(__half2*)&C[(size_t)(r + 8) * ldc + c] = __floats2half2_rn(e2, e3);
                rs0 += e0 + e1;
                rs1 += e2 + e3;
            }
            rs0 += __shfl_xor_sync(0xffffffffu, rs0, 1);
            rs0 += __shfl_xor_sync(0xffffffffu, rs0, 2);
            rs1 += __shfl_xor_sync(0xffffffffu, rs1, 1);
            rs1 += __shfl_xor_sync(0xffffffffu, rs1, 2);
            if (tg == 0) {
                atomicAdd(&srs[wm + mi * 16 + g], rs0);
                atomicAdd(&srs[wm + mi * 16 + g + 8], rs1);
            }
        }
        __syncthreads();
        if (tid < 128)
            rs[((size_t)blockIdx.z * 1024 + q0 + tid) * 8 + blockIdx.x] = srs[tid];
    } else {
        // EPI == 2: sum 8 partials per row, scale by 1/rowsum
        const float* rsb = rs + ((size_t)blockIdx.z * 1024 + blockIdx.y * 128) * 8;
#pragma unroll
        for (int mi = 0; mi < 4; mi++) {
            const int r = wm + mi * 16 + g;
            float4 p0 = *(const float4*)&rsb[(size_t)r * 8];
            float4 p1 = *(const float4*)&rsb[(size_t)r * 8 + 4];
            const float inv0 = 1.0f / (p0.x + p0.y + p0.z + p0.w +
                                       p1.x + p1.y + p1.z + p1.w);
            float4 q0v = *(const float4*)&rsb[(size_t)(r + 8) * 8];
            float4 q1v = *(const float4*)&rsb[(size_t)(r + 8) * 8 + 4];
            const float inv1 = 1.0f / (q0v.x + q0v.y + q0v.z + q0v.w +
                                       q1v.x + q1v.y + q1v.z + q1v.w);
#pragma unroll
            for (int ni = 0; ni < 4; ni++) {
                const int c = wn + ni * 8 + tg * 2;
                *(__half2*)&C[(size_t)r * ldc + c] =
                    __floats2half2_rn(inv0 * acc[mi][ni][0], inv0 * acc[mi][ni][1]);
                *(__half2*)&C[(size_t)(r + 8) * ldc + c] =
                    __floats2half2_rn(inv1 * acc[mi][ni][2], inv1 * acc[mi][ni][3]);
            }
        }
    }
}

// ---------------- merged converts / transposes ----------
__global__ __launch_bounds__(256) void k_f2h3(
    const float* __restrict__ i0, const float* __restrict__ i1,
    const float* __restrict__ i2,
    __half* __restrict__ o0, __half* __restrict__ o1, __half* __restrict__ o2)
{
    const float* in  = (blockIdx.y == 0) ? i0 : (blockIdx.y == 1) ? i1 : i2;
    __half*      out = (blockIdx.y == 0) ? o0 : (blockIdx.y == 1) ? o1 : o2;
    const int i = (blockIdx.x * 256 + threadIdx.x) * 4;
    float4 v = *(const float4*)&in[i];
    ((__half2*)(out + i))[0] = __floats2half2_rn(v.x, v.y);
    ((__half2*)(out + i))[1] = __floats2half2_rn(v.z, v.w);
}

// Transpose fp32 [R,C] -> fp16 [C,R].  grid(C/32, R/32, nmat), block(32,8).
__global__ void k_wtrans3_h(
    const float* __restrict__ i0, const float* __restrict__ i1,
    const float* __restrict__ i2,
    __half* __restrict__ o0, __half* __restrict__ o1, __half* __restrict__ o2,
    int R, int C)
{
    const float* in  = (blockIdx.z == 0) ? i0 : (blockIdx.z == 1) ? i1 : i2;
    __half*      out = (blockIdx.z == 0) ? o0 : (blockIdx.z == 1) ? o1 : o2;
    __shared__ float t[32][33];
    const int c0 = blockIdx.x * 32, r0 = blockIdx.y * 32;
    const int tx = threadIdx.x, ty = threadIdx.y;
#pragma unroll
    for (int i = 0; i < 32; i += 8)
        t[ty + i][tx] = in[(size_t)(r0 + ty + i) * C + c0 + tx];
    __syncthreads();
#pragma unroll
    for (int i = 0; i < 32; i += 8)
        out[(size_t)(c0 + ty + i) * R + r0 + tx] = __float2half(t[tx][ty + i]);
}

__global__ void k_wtrans_h(const float* __restrict__ in, __half* __restrict__ out,
                           int R, int C)
{
    __shared__ float t[32][33];
    const int c0 = blockIdx.x * 32, r0 = blockIdx.y * 32;
    const int tx = threadIdx.x, ty = threadIdx.y;
#pragma unroll
    for (int i = 0; i < 32; i += 8)
        t[ty + i][tx] = in[(size_t)(r0 + ty + i) * C + c0 + tx];
    __syncthreads();
#pragma unroll
    for (int i = 0; i < 32; i += 8)
        out[(size_t)(c0 + ty + i) * R + r0 + tx] = __float2half(t[tx][ty + i]);
}

// ---------------- layernorm -----------------------
__global__ __launch_bounds__(256) void k_ln(
    const float* __restrict__ X, const float* __restrict__ gamma,
    const float* __restrict__ beta, float* __restrict__ Y)
{
    const int r = blockIdx.x;
    const float* x = X + (size_t)r * DMODEL;
    const int tid = threadIdx.x;
    float v0 = x[tid];
    float v1 = x[tid + 256];
    float s  = v0 + v1;
    float ss = v0 * v0 + v1 * v1;

    __shared__ float shs[8];
    __shared__ float shss[8];
#pragma unroll
    for (int off = 16; off; off >>= 1) {
        s  += __shfl_xor_sync(0xffffffffu, s,  off);
        ss += __shfl_xor_sync(0xffffffffu, ss, off);
    }
    if ((tid & 31) == 0) { shs[tid >> 5] = s; shss[tid >> 5] = ss; }
    __syncthreads();
    s = 0.0f; ss = 0.0f;
#pragma unroll
    for (int w = 0; w < 8; w++) { s += shs[w]; ss += shss[w]; }

    const float mean = s * (1.0f / 512.0f);
    const float var  = ss * (1.0f / 512.0f) - mean * mean;
    const float rstd = rsqrtf(var + 1e-5f);

    Y[(size_t)r * DMODEL + tid]       = (v0 - mean) * rstd * gamma[tid]       + beta[tid];
    Y[(size_t)r * DMODEL + tid + 256] = (v1 - mean) * rstd * gamma[tid + 256] + beta[tid + 256];
}

// ---------------- launch --------------------------
extern "C" void kernel_launch(void* const* d_in, const int* in_sizes, int n_in,
                              void* d_out, int out_size)
{
    const float* q     = (const float*)d_in[0];
    const float* k     = (const float*)d_in[1];
    const float* v     = (const float*)d_in[2];
    const float* Wq    = (const float*)d_in[3];
    const float* Wk    = (const float*)d_in[4];
    const float* Wv    = (const float*)d_in[5];
    const float* Wo    = (const float*)d_in[6];
    const float* gamma = (const float*)d_in[7];
    const float* beta  = (const float*)d_in[8];
    const unsigned char* mask = (const unsigned char*)d_in[9];
    float* out = (float*)d_out;

    __half *qk16, *v16, *wqk, *wvt, *wot, *qkh, *vht, *pr, *ao;
    float *og, *rsp;
    cudaGetSymbolAddress((void**)&qk16, g_qk16);
    cudaGetSymbolAddress((void**)&v16,  g_v16);
    cudaGetSymbolAddress((void**)&wqk,  g_wqk16);
    cudaGetSymbolAddress((void**)&wvt,  g_wvt16);
    cudaGetSymbolAddress((void**)&wot,  g_wot16);
    cudaGetSymbolAddress((void**)&qkh,  g_qkh16);
    cudaGetSymbolAddress((void**)&vht,  g_vht16);
    cudaGetSymbolAddress((void**)&pr,   g_pr16);
    cudaGetSymbolAddress((void**)&ao,   g_ao16);
    cudaGetSymbolAddress((void**)&og,   g_og);
    cudaGetSymbolAddress((void**)&rsp,  g_rsp);

    cudaFuncSetAttribute((k_gemm_h<__half, 0>), cudaFuncAttributeMaxDynamicSharedMemorySize, GSMEM);
    cudaFuncSetAttribute((k_gemm_h<__half, 1>), cudaFuncAttributeMaxDynamicSharedMemorySize, GSMEM);
    cudaFuncSetAttribute((k_gemm_h<__half, 2>), cudaFuncAttributeMaxDynamicSharedMemorySize, GSMEM);
    cudaFuncSetAttribute((k_gemm_h<float, 0>),  cudaFuncAttributeMaxDynamicSharedMemorySize, GSMEM);

    // fp32 -> fp16 converts (q -> qk16[0:], k -> qk16[4194304:], v -> v16)
    k_f2h3<<<dim3(4096, 3), 256>>>(q, k, v, qk16, qk16 + 4194304, v16);

    // transposed fp16 weights (Wq/Wk into wqk halves; Wv, Wo separate)
    const dim3 tb(32, 8);
    k_wtrans3_h<<<dim3(HDH / 32, DMODEL / 32, 3), tb>>>(
        Wq, Wk, Wv, wqk, wqk + 2097152, wvt, DMODEL, HDH);
    k_wtrans_h<<<dim3(DMODEL / 32, HDH / 32), tb>>>(Wo, wot, HDH, DMODEL);

    // Q + K projections, one launch, head-separated output.
    // z1 = z>>3 in {0,1} selects Q/K; z2 = z&7 = head.
    // qkh[z1][h][b*1024+s][d] = sum_k qk16[z1][b*1024+s][k] * wqk[z1][h*512+d][k]
    k_gemm_h<__half, 0><<<dim3(512 / 128, ROWS / 128, 16), 256, GSMEM>>>(
        qk16, DMODEL, 4194304, 0,
        wqk,  DMODEL, 2097152, (size_t)512 * DMODEL,
        qkh,  512, 33554432, (size_t)ROWS * 512,
        DMODEL, 1.0f, nullptr, nullptr);

    // V projection transposed: vht[h,b][d][s] = sum_k WvT[h*512+d,k] * v16[b*1024+s,k]
    k_gemm_h<__half, 0><<<dim3(SEQ / 128, 512 / 128, NHB), 256, GSMEM>>>(
        wvt, DMODEL, (size_t)512 * DMODEL, 0,
        v16, DMODEL, 0, (size_t)SEQ * DMODEL,
        vht, SEQ, (size_t)8 * 512 * SEQ, (size_t)512 * SEQ,
        DMODEL, 1.0f, nullptr, nullptr);

    // scores -> masked exp fp16 (pr) + row-sum partials, fused.
    // Operands head-separated, contiguous lda=512. z1 = h, z2 = b.
    const float inv_temp = 1.0f / sqrtf(512.0f);
    k_gemm_h<__half, 1><<<dim3(SEQ / 128, SEQ / 128, NHB), 256, GSMEM>>>(
        qkh, 512, (size_t)ROWS * 512, (size_t)SEQ * 512,
        qkh + 33554432, 512, (size_t)ROWS * 512, (size_t)SEQ * 512,
        pr, SEQ, (size_t)8 * SEQ * SEQ, (size_t)SEQ * SEQ,
        DMODEL, inv_temp, mask, rsp);

    // PV with fused partial-sum reduction + 1/rowsum normalization
    k_gemm_h<__half, 2><<<dim3(512 / 128, SEQ / 128, NHB), 256, GSMEM>>>(
        pr, SEQ, (size_t)8 * SEQ * SEQ, (size_t)SEQ * SEQ,
        vht, SEQ, (size_t)8 * 512 * SEQ, (size_t)512 * SEQ,
        ao, HDH, 512, (size_t)SEQ * HDH,
        SEQ, 1.0f, nullptr, rsp);

    // O projection
    k_gemm_h<float, 0><<<dim3(DMODEL / 128, ROWS / 128, 1), 256, GSMEM>>>(
        ao, HDH, 0, 0, wot, HDH, 0, 0, og, DMODEL, 0, 0, HDH, 1.0f,
        nullptr, nullptr);

    // LayerNorm
    k_ln<<<ROWS, 256>>>(og, gamma, beta, out);
}